// round 11
// baseline (speedup 1.0000x reference)
#include <cuda_runtime.h>
#include <cuda_bf16.h>

#define BATCH 8
#define SEQ   512
#define HID   1024
#define NHEAD 16
#define HD    64
#define MROWS (BATCH*SEQ)

__device__ float g_q[BATCH*NHEAD*SEQ*HD];
__device__ float g_k[BATCH*NHEAD*SEQ*HD];
__device__ float g_v[BATCH*NHEAD*SEQ*HD];
__device__ float g_attn[BATCH*SEQ*HID];

// tf32-bit pre-converted operands for the projection GEMMs
__device__ unsigned g_qt[MROWS*HID];     // query  (tf32 bits)
__device__ unsigned g_kt[MROWS*HID];     // key
__device__ unsigned g_vt[MROWS*HID];     // value
__device__ unsigned g_at[MROWS*HID];     // attn output
__device__ unsigned g_wt[4*HID*HID];     // Wq,Wk,Wv,Wo

__device__ __forceinline__ unsigned f2tf(float f) {
    unsigned u;
    asm("cvt.rna.tf32.f32 %0, %1;" : "=r"(u) : "f"(f));
    return u;
}

__device__ __forceinline__ void mma8(float* c, const unsigned* a, const unsigned* b) {
    asm volatile(
        "mma.sync.aligned.m16n8k8.row.col.f32.tf32.tf32.f32 "
        "{%0,%1,%2,%3}, {%4,%5,%6,%7}, {%8,%9}, {%0,%1,%2,%3};"
        : "+f"(c[0]), "+f"(c[1]), "+f"(c[2]), "+f"(c[3])
        : "r"(a[0]), "r"(a[1]), "r"(a[2]), "r"(a[3]), "r"(b[0]), "r"(b[1]));
}

__device__ __forceinline__ void cp_async16(unsigned saddr, const void* gptr) {
    asm volatile("cp.async.cg.shared.global [%0], [%1], 16;"
                 :: "r"(saddr), "l"(gptr));
}
__device__ __forceinline__ void cp_commit() {
    asm volatile("cp.async.commit_group;");
}
__device__ __forceinline__ void cp_wait0() {
    asm volatile("cp.async.wait_group 0;");
}

// ===========================================================================
// Elementwise fp32 -> tf32-bits conversion passes
// ===========================================================================
#define NF4_A ((MROWS*HID)/4)   // 1,048,576 float4 per activation tensor
#define NF4_W ((HID*HID)/4)     // 262,144 float4 per weight

__global__ __launch_bounds__(256)
void conv_inputs(const float* __restrict__ q, const float* __restrict__ k,
                 const float* __restrict__ v, const float* __restrict__ wq,
                 const float* __restrict__ wk, const float* __restrict__ wv,
                 const float* __restrict__ wo)
{
    const long total = 3L * NF4_A + 4L * NF4_W;
    for (long i = blockIdx.x * 256L + threadIdx.x; i < total; i += gridDim.x * 256L) {
        const float4* src;
        unsigned* dst;
        long j = i;
        if (j < NF4_A)                 { src = (const float4*)q;  dst = g_qt; }
        else if ((j -= NF4_A) < NF4_A) { src = (const float4*)k;  dst = g_kt; }
        else if ((j -= NF4_A) < NF4_A) { src = (const float4*)v;  dst = g_vt; }
        else {
            j -= NF4_A;
            const int w = (int)(j / NF4_W);
            j -= (long)w * NF4_W;
            src = (const float4*)((w == 0) ? wq : (w == 1) ? wk : (w == 2) ? wv : wo);
            dst = g_wt + (long)w * (HID*HID);
        }
        const float4 x = src[j];
        uint4 y;
        y.x = f2tf(x.x); y.y = f2tf(x.y); y.z = f2tf(x.z); y.w = f2tf(x.w);
        *(uint4*)(dst + j * 4) = y;
    }
}

__global__ __launch_bounds__(256)
void conv_attn()
{
    for (long i = blockIdx.x * 256L + threadIdx.x; i < NF4_A; i += gridDim.x * 256L) {
        const float4 x = *(const float4*)(g_attn + i * 4);
        uint4 y;
        y.x = f2tf(x.x); y.y = f2tf(x.y); y.z = f2tf(x.z); y.w = f2tf(x.w);
        *(uint4*)(g_at + i * 4) = y;
    }
}

// ===========================================================================
// tf32 tensor-core GEMM, cp.async mainloop on pre-converted operands.
// C[m,n] = scale * (sum_k A[m,k]*W[n,k] + bias[n]); dst 0..2 scatter, 3 plain
// ===========================================================================
#define GBK 16
#define KPAD 20

__global__ __launch_bounds__(256, 2)
void gemm_tf32(int asel, int wsel,
               const float* __restrict__ bias, float* __restrict__ Cout,
               float scale, int dst)
{
    __shared__ __align__(16) unsigned As[2][128 * KPAD];
    __shared__ __align__(16) unsigned Bs[2][128 * KPAD];

    const unsigned* Asrc = (asel == 0) ? g_qt : (asel == 1) ? g_kt
                         : (asel == 2) ? g_vt : g_at;
    const unsigned* Wsrc = g_wt + (long)wsel * (HID*HID);

    const int tid = threadIdx.x;
    const int bm = blockIdx.y * 128;
    const int bn = blockIdx.x * 128;
    const int wid = tid >> 5, lane = tid & 31;
    const int wm = (wid >> 2) * 64;
    const int wn = (wid & 3) * 32;
    const int gp = lane >> 2;
    const int tg = lane & 3;

    const int r0 = tid >> 2;          // 0..63
    const int c0 = (tid & 3) * 4;     // 0,4,8,12

    const unsigned* A0 = Asrc + (long)(bm + r0)      * 1024 + c0;
    const unsigned* A1 = Asrc + (long)(bm + r0 + 64) * 1024 + c0;
    const unsigned* W0 = Wsrc + (long)(bn + r0)      * 1024 + c0;
    const unsigned* W1 = Wsrc + (long)(bn + r0 + 64) * 1024 + c0;

    const unsigned as_base = (unsigned)__cvta_generic_to_shared(As);
    const unsigned bs_base = (unsigned)__cvta_generic_to_shared(Bs);
    const unsigned soff0 = (unsigned)(( r0       * KPAD + c0) * 4);
    const unsigned soff1 = (unsigned)(((r0 + 64) * KPAD + c0) * 4);
    const unsigned bufstride = 128 * KPAD * 4;

    float acc[4][4][4];
    #pragma unroll
    for (int i = 0; i < 4; i++)
        #pragma unroll
        for (int j = 0; j < 4; j++)
            #pragma unroll
            for (int k = 0; k < 4; k++) acc[i][j][k] = 0.f;

    // prologue: tile 0 -> buffer 0
    cp_async16(as_base + soff0, A0);
    cp_async16(as_base + soff1, A1);
    cp_async16(bs_base + soff0, W0);
    cp_async16(bs_base + soff1, W1);
    cp_commit();
    cp_wait0();
    __syncthreads();

    int buf = 0;
    const int KT = 1024 / GBK;   // 64
    for (int t = 0; t < KT; ++t) {
        if (t < KT - 1) {
            const unsigned bo = (unsigned)(buf ^ 1) * bufstride;
            const int ko = (t + 1) * GBK;
            cp_async16(as_base + bo + soff0, A0 + ko);
            cp_async16(as_base + bo + soff1, A1 + ko);
            cp_async16(bs_base + bo + soff0, W0 + ko);
            cp_async16(bs_base + bo + soff1, W1 + ko);
            cp_commit();
        }
        const unsigned* as = As[buf];
        const unsigned* bs = Bs[buf];
        #pragma unroll
        for (int ks = 0; ks < 2; ks++) {
            const int kb = ks * 8;
            unsigned af[4][4], bf[4][2];
            #pragma unroll
            for (int mf = 0; mf < 4; mf++) {
                const int row = wm + mf * 16 + gp;
                af[mf][0] = as[ row      * KPAD + kb + tg];
                af[mf][1] = as[(row + 8) * KPAD + kb + tg];
                af[mf][2] = as[ row      * KPAD + kb + tg + 4];
                af[mf][3] = as[(row + 8) * KPAD + kb + tg + 4];
            }
            #pragma unroll
            for (int nf = 0; nf < 4; nf++) {
                const int row = wn + nf * 8 + gp;
                bf[nf][0] = bs[row * KPAD + kb + tg];
                bf[nf][1] = bs[row * KPAD + kb + tg + 4];
            }
            #pragma unroll
            for (int mf = 0; mf < 4; mf++)
                #pragma unroll
                for (int nf = 0; nf < 4; nf++)
                    mma8(acc[mf][nf], af[mf], bf[nf]);
        }
        if (t < KT - 1) {
            cp_wait0();
            __syncthreads();
        }
        buf ^= 1;
    }

    float* Cq = (dst == 0) ? g_q : (dst == 1) ? g_k : g_v;

    #pragma unroll
    for (int mf = 0; mf < 4; mf++) {
        #pragma unroll
        for (int nf = 0; nf < 4; nf++) {
            const int n0 = bn + wn + nf * 8 + tg * 2;
            const float b0 = bias[n0], b1 = bias[n0 + 1];
            #pragma unroll
            for (int half = 0; half < 2; half++) {
                const int m = bm + wm + mf * 16 + gp + half * 8;
                const float v0 = (acc[mf][nf][half * 2 + 0] + b0) * scale;
                const float v1 = (acc[mf][nf][half * 2 + 1] + b1) * scale;
                if (dst < 3) {
                    const int b = m >> 9, s = m & 511;
                    const int h = n0 >> 6, d = n0 & 63;
                    const long base = (((long)(b * NHEAD + h)) * SEQ + s) * HD;
                    Cq[base + d]     = v0;
                    Cq[base + d + 1] = v1;
                } else {
                    Cout[(long)m * HID + n0]     = v0;
                    Cout[(long)m * HID + n0 + 1] = v1;
                }
            }
        }
    }
}

// ===========================================================================
// tf32 mma fused attention (unchanged from R10 best).
// QT=32, 2 CTA/SM, double-buffered K/V via cp.async (raw-fp32 truncation).
// ===========================================================================
#define QT   32
#define SCP  516
#define KP   68
#define VP   72
#define KVBUF (64 * 72)
#define SMEM_ATTN ((QT*SCP + 2*KVBUF) * (int)sizeof(float))

__global__ __launch_bounds__(256, 2)
void attn_mma(const float* __restrict__ mask, const float* __restrict__ kg,
              const int* __restrict__ lena, const float* __restrict__ hy,
              const int* __restrict__ layer_p)
{
    extern __shared__ float sm[];
    float*    sc = sm;                              // [32][516]
    unsigned* kv = (unsigned*)(sm + QT * SCP);      // 2 buffers of 64x72

    const unsigned kv_u32 = (unsigned)__cvta_generic_to_shared(kv);

    const int tid = threadIdx.x;
    const int bh = blockIdx.x;
    const int b = bh >> 4, h = bh & 15;
    const int q0 = blockIdx.y * QT;

    const long head_off = ((long)(b * NHEAD + h)) * SEQ * HD;

    const int wid = tid >> 5, lane = tid & 31;
    const int g8 = lane >> 2;
    const int tg = lane & 3;
    const int wm = (wid >> 2) * 16;
    const int wn = (wid & 3) * 16;

    const int lr = tid >> 2;
    const int lcb = (tid & 3) * 16;

    unsigned qa[8][4];
    {
        const float* q_r0 = g_q + head_off + (long)(q0 + wm + g8)     * HD;
        const float* q_r1 = g_q + head_off + (long)(q0 + wm + g8 + 8) * HD;
        #pragma unroll
        for (int kb = 0; kb < 8; kb++) {
            qa[kb][0] = f2tf(q_r0[kb * 8 + tg]);
            qa[kb][1] = f2tf(q_r1[kb * 8 + tg]);
            qa[kb][2] = f2tf(q_r0[kb * 8 + tg + 4]);
            qa[kb][3] = f2tf(q_r1[kb * 8 + tg + 4]);
        }
    }

    // ================= Phase 1: scores = Q K^T + mask =================
    {
        const float* kbase = g_k + head_off + (long)lr * HD + lcb;
        const unsigned kdst = kv_u32 + (unsigned)((lr * KP + lcb) * 4);

        #pragma unroll
        for (int i = 0; i < 4; i++)
            cp_async16(kdst + i * 16, kbase + i * 4);
        cp_commit();
        cp_wait0();
        __syncthreads();

        for (int kt = 0; kt < 8; kt++) {
            if (kt < 7) {
                const unsigned d = kv_u32 + (unsigned)(((kt + 1) & 1) * KVBUF * 4)
                                 + (unsigned)((lr * KP + lcb) * 4);
                const float* s = kbase + (long)(kt + 1) * 64 * HD;
                #pragma unroll
                for (int i = 0; i < 4; i++)
                    cp_async16(d + i * 16, s + i * 4);
                cp_commit();
            }
            const unsigned* kbuf = kv + (kt & 1) * KVBUF;

            float acc[2][4];
            #pragma unroll
            for (int nf = 0; nf < 2; nf++)
                #pragma unroll
                for (int k = 0; k < 4; k++) acc[nf][k] = 0.f;

            #pragma unroll
            for (int kb = 0; kb < 8; kb++) {
                unsigned bf[2][2];
                #pragma unroll
                for (int nf = 0; nf < 2; nf++) {
                    const unsigned* base = kbuf + (wn + nf * 8 + g8) * KP + kb * 8 + tg;
                    bf[nf][0] = base[0];
                    bf[nf][1] = base[4];
                }
                #pragma unroll
                for (int nf = 0; nf < 2; nf++)
                    mma8(acc[nf], qa[kb], bf[nf]);
            }

            #pragma unroll
            for (int nf = 0; nf < 2; nf++) {
                const int c = kt * 64 + wn + nf * 8 + 2 * tg;
                #pragma unroll
                for (int half = 0; half < 2; half++) {
                    const int r = wm + g8 + half * 8;
                    const float2 mv = *(const float2*)(mask + ((long)b * SEQ + (q0 + r)) * SEQ + c);
                    float2 sv;
                    sv.x = acc[nf][half * 2 + 0] + mv.x;
                    sv.y = acc[nf][half * 2 + 1] + mv.y;
                    *(float2*)(sc + r * SCP + c) = sv;
                }
            }

            if (kt < 7) {
                cp_wait0();
                __syncthreads();
            }
        }
    }
    __syncthreads();

    // ================= Phase 2: softmax + probs mods =================
    {
        const int l  = lena[b];
        const int ly = *layer_p;
        const float ha = hy[ly * 3 + 0];
        const float hb = hy[ly * 3 + 1];
        const float hc = hy[ly * 3 + 2];
        const float* simp = kg + (long)b * 2 * SEQ * SEQ;
        const float* topp = simp + (long)SEQ * SEQ;

        for (int r = wid; r < QT; r += 8) {
            float* row = sc + r * SCP;
            const int qg = q0 + r;

            float mx = -1e30f;
            #pragma unroll
            for (int j0 = lane * 2; j0 < SEQ; j0 += 64) {
                const float2 v = *(const float2*)(row + j0);
                mx = fmaxf(mx, fmaxf(v.x, v.y));
            }
            #pragma unroll
            for (int o = 16; o > 0; o >>= 1) mx = fmaxf(mx, __shfl_xor_sync(0xffffffffu, mx, o));

            float s = 0.f;
            #pragma unroll
            for (int j0 = lane * 2; j0 < SEQ; j0 += 64) {
                float2 v = *(const float2*)(row + j0);
                v.x = __expf(v.x - mx);
                v.y = __expf(v.y - mx);
                *(float2*)(row + j0) = v;
                s += v.x + v.y;
            }
            #pragma unroll
            for (int o = 16; o > 0; o >>= 1) s += __shfl_xor_sync(0xffffffffu, s, o);
            const float inv = 1.0f / s;

            const bool ra_q = (qg >= 1) && (qg < l - 1);
            const bool ca_q = (qg >= l) && (qg < SEQ - 1);
            const long krow = (long)qg * SEQ;
            #pragma unroll
            for (int j0 = lane * 2; j0 < SEQ; j0 += 64) {
                float2 v = *(const float2*)(row + j0);
                const float2 sv = *(const float2*)(simp + krow + j0);
                const float2 tv = *(const float2*)(topp + krow + j0);
                const int j1 = j0 + 1;
                const bool ra_0 = (j0 >= 1) && (j0 < l - 1);
                const bool ca_0 = (j0 >= l) && (j0 < SEQ - 1);
                const bool ra_1 = (j1 >= 1) && (j1 < l - 1);
                const bool ca_1 = (j1 >= l) && (j1 < SEQ - 1);
                const float lg0 = ((ra_q && ca_0) || (ra_0 && ca_q)) ? hc : 1.0f;
                const float lg1 = ((ra_q && ca_1) || (ra_1 && ca_q)) ? hc : 1.0f;
                float2 p;
                p.x = __uint_as_float(f2tf(v.x * inv * lg0 + ha * sv.x + hb * tv.x));
                p.y = __uint_as_float(f2tf(v.y * inv * lg1 + ha * sv.y + hb * tv.y));
                *(float2*)(row + j0) = p;
            }
        }
    }

    // ================= Phase 3: out = P V =================
    {
        float oacc[2][4];
        #pragma unroll
        for (int nf = 0; nf < 2; nf++)
            #pragma unroll
            for (int k = 0; k < 4; k++) oacc[nf][k] = 0.f;

        const float* vbase = g_v + head_off + (long)lr * HD + lcb;
        const unsigned vdst = kv_u32 + (unsigned)((lr * VP + lcb) * 4);

        #pragma unroll
        for (int i = 0; i < 4; i++)
            cp_async16(vdst + i * 16, vbase + i * 4);
        cp_commit();
        cp_wait0();
        __syncthreads();

        for (int kt = 0; kt < 8; kt++) {
            if (kt < 7) {
                const unsigned d = kv_u32 + (unsigned)(((kt + 1) & 1) * KVBUF * 4)
                                 + (unsigned)((lr * VP + lcb) * 4);
                const float* s = vbase + (long)(kt + 1) * 64 * HD;
                #pragma unroll
                for (int i = 0; i < 4; i++)
                    cp_async16(d + i * 16, s + i * 4);
                cp_commit();
            }
            const unsigned* vbuf = kv + (kt & 1) * KVBUF;

            #pragma unroll
            for (int kb = 0; kb < 8; kb++) {
                unsigned af[4], bf[2][2];
                {
                    const float* base = sc + (wm + g8) * SCP + kt * 64 + kb * 8 + tg;
                    af[0] = __float_as_uint(base[0]);
                    af[1] = __float_as_uint(base[8 * SCP]);
                    af[2] = __float_as_uint(base[4]);
                    af[3] = __float_as_uint(base[8 * SCP + 4]);
                }
                #pragma unroll
                for (int nf = 0; nf < 2; nf++) {
                    const unsigned* base = vbuf + (kb * 8 + tg) * VP + wn + nf * 8 + g8;
                    bf[nf][0] = base[0];
                    bf[nf][1] = base[4 * VP];
                }
                #pragma unroll
                for (int nf = 0; nf < 2; nf++)
                    mma8(oacc[nf], af, bf[nf]);
            }

            if (kt < 7) {
                cp_wait0();
                __syncthreads();
            }
        }

        #pragma unroll
        for (int nf = 0; nf < 2; nf++) {
            const int d0 = wn + nf * 8 + 2 * tg;
            #pragma unroll
            for (int half = 0; half < 2; half++) {
                const int r = q0 + wm + g8 + half * 8;
                float2 ov;
                ov.x = oacc[nf][half * 2 + 0];
                ov.y = oacc[nf][half * 2 + 1];
                *(float2*)(g_attn + ((long)b * SEQ + r) * HID + h * HD + d0) = ov;
            }
        }
    }
}

// ===========================================================================
extern "C" void kernel_launch(void* const* d_in, const int* in_sizes, int n_in,
                              void* d_out, int out_size)
{
    const float* query = (const float*)d_in[0];
    const float* key   = (const float*)d_in[1];
    const float* value = (const float*)d_in[2];
    const float* mask  = (const float*)d_in[3];
    const int*   lena  = (const int*)  d_in[4];
    const float* kg    = (const float*)d_in[5];
    const float* hy    = (const float*)d_in[6];
    const int*   layer = (const int*)  d_in[7];
    const float* Wq    = (const float*)d_in[8];
    const float* bq    = (const float*)d_in[9];
    const float* Wk    = (const float*)d_in[10];
    const float* bk    = (const float*)d_in[11];
    const float* Wv    = (const float*)d_in[12];
    const float* bv    = (const float*)d_in[13];
    const float* Wo    = (const float*)d_in[14];
    const float* bo    = (const float*)d_in[15];
    float* out = (float*)d_out;

    static int smem_set = 0;
    if (!smem_set) {
        cudaFuncSetAttribute(attn_mma,
                             cudaFuncAttributeMaxDynamicSharedMemorySize, SMEM_ATTN);
        smem_set = 1;
    }

    const dim3 ggrid(HID / 128, MROWS / 128);   // (8, 32)
    const float qscale = 0.125f;                // 1/sqrt(64)

    conv_inputs<<<4096, 256>>>(query, key, value, Wq, Wk, Wv, Wo);

    gemm_tf32<<<ggrid, 256>>>(0, 0, bq, nullptr, qscale, 0);
    gemm_tf32<<<ggrid, 256>>>(1, 1, bk, nullptr, 1.0f,   1);
    gemm_tf32<<<ggrid, 256>>>(2, 2, bv, nullptr, 1.0f,   2);

    dim3 attn_grid(BATCH * NHEAD, SEQ / QT);    // (128, 16)
    attn_mma<<<attn_grid, 256, SMEM_ATTN>>>(mask, kg, lena, hy, layer);

    conv_attn<<<1024, 256>>>();

    gemm_tf32<<<ggrid, 256>>>(3, 3, bo, out, 1.0f, 3);
}

// round 12
// speedup vs baseline: 1.0850x; 1.0850x over previous
#include <cuda_runtime.h>
#include <cuda_bf16.h>

#define BATCH 8
#define SEQ   512
#define HID   1024
#define NHEAD 16
#define HD    64
#define MROWS (BATCH*SEQ)

__device__ float g_q[BATCH*NHEAD*SEQ*HD];
__device__ float g_k[BATCH*NHEAD*SEQ*HD];
__device__ float g_v[BATCH*NHEAD*SEQ*HD];

// tf32-bit pre-converted operands for the projection GEMMs
__device__ unsigned g_qt[MROWS*HID];     // query  (tf32 bits)
__device__ unsigned g_kt[MROWS*HID];     // key
__device__ unsigned g_vt[MROWS*HID];     // value
__device__ unsigned g_at[MROWS*HID];     // attn output (tf32 bits, written by attn_mma)
__device__ unsigned g_wt[4*HID*HID];     // Wq,Wk,Wv,Wo

__device__ __forceinline__ unsigned f2tf(float f) {
    unsigned u;
    asm("cvt.rna.tf32.f32 %0, %1;" : "=r"(u) : "f"(f));
    return u;
}

__device__ __forceinline__ void mma8(float* c, const unsigned* a, const unsigned* b) {
    asm volatile(
        "mma.sync.aligned.m16n8k8.row.col.f32.tf32.tf32.f32 "
        "{%0,%1,%2,%3}, {%4,%5,%6,%7}, {%8,%9}, {%0,%1,%2,%3};"
        : "+f"(c[0]), "+f"(c[1]), "+f"(c[2]), "+f"(c[3])
        : "r"(a[0]), "r"(a[1]), "r"(a[2]), "r"(a[3]), "r"(b[0]), "r"(b[1]));
}

__device__ __forceinline__ void cp_async16(unsigned saddr, const void* gptr) {
    asm volatile("cp.async.cg.shared.global [%0], [%1], 16;"
                 :: "r"(saddr), "l"(gptr));
}
__device__ __forceinline__ void cp_commit() {
    asm volatile("cp.async.commit_group;");
}
__device__ __forceinline__ void cp_wait0() {
    asm volatile("cp.async.wait_group 0;");
}
__device__ __forceinline__ void cp_wait2() {
    asm volatile("cp.async.wait_group 2;");
}

// ===========================================================================
// Elementwise fp32 -> tf32-bits conversion for inputs + weights
// ===========================================================================
#define NF4_A ((MROWS*HID)/4)
#define NF4_W ((HID*HID)/4)

__global__ __launch_bounds__(256)
void conv_inputs(const float* __restrict__ q, const float* __restrict__ k,
                 const float* __restrict__ v, const float* __restrict__ wq,
                 const float* __restrict__ wk, const float* __restrict__ wv,
                 const float* __restrict__ wo)
{
    const long total = 3L * NF4_A + 4L * NF4_W;
    for (long i = blockIdx.x * 256L + threadIdx.x; i < total; i += gridDim.x * 256L) {
        const float4* src;
        unsigned* dst;
        long j = i;
        if (j < NF4_A)                 { src = (const float4*)q;  dst = g_qt; }
        else if ((j -= NF4_A) < NF4_A) { src = (const float4*)k;  dst = g_kt; }
        else if ((j -= NF4_A) < NF4_A) { src = (const float4*)v;  dst = g_vt; }
        else {
            j -= NF4_A;
            const int w = (int)(j / NF4_W);
            j -= (long)w * NF4_W;
            src = (const float4*)((w == 0) ? wq : (w == 1) ? wk : (w == 2) ? wv : wo);
            dst = g_wt + (long)w * (HID*HID);
        }
        const float4 x = src[j];
        uint4 y;
        y.x = f2tf(x.x); y.y = f2tf(x.y); y.z = f2tf(x.z); y.w = f2tf(x.w);
        *(uint4*)(dst + j * 4) = y;
    }
}

// ===========================================================================
// tf32 tensor-core GEMM, 4-stage cp.async pipeline on pre-converted operands.
// C[m,n] = scale * (sum_k A[m,k]*W[n,k] + bias[n]); dst 0..2 scatter, 3 plain
// Dynamic smem: 4 stages x (A+B) x 128x20 u32 = 81,920 B -> 2 CTA/SM.
// ===========================================================================
#define GBK 16
#define KPAD 20
#define STG_ELEMS (128 * KPAD)                 // per array per stage
#define SMEM_GEMM (8 * STG_ELEMS * (int)sizeof(unsigned))   // 4 stages x 2 arrays

__global__ __launch_bounds__(256, 2)
void gemm_tf32(int asel, int wsel,
               const float* __restrict__ bias, float* __restrict__ Cout,
               float scale, int dst)
{
    extern __shared__ __align__(16) unsigned smg[];
    unsigned* As = smg;                         // 4 stages
    unsigned* Bs = smg + 4 * STG_ELEMS;         // 4 stages

    const unsigned* Asrc = (asel == 0) ? g_qt : (asel == 1) ? g_kt
                         : (asel == 2) ? g_vt : g_at;
    const unsigned* Wsrc = g_wt + (long)wsel * (HID*HID);

    const int tid = threadIdx.x;
    const int bm = blockIdx.y * 128;
    const int bn = blockIdx.x * 128;
    const int wid = tid >> 5, lane = tid & 31;
    const int wm = (wid >> 2) * 64;
    const int wn = (wid & 3) * 32;
    const int gp = lane >> 2;
    const int tg = lane & 3;

    const int r0 = tid >> 2;          // 0..63
    const int c0 = (tid & 3) * 4;     // 0,4,8,12

    const unsigned* A0 = Asrc + (long)(bm + r0)      * 1024 + c0;
    const unsigned* A1 = Asrc + (long)(bm + r0 + 64) * 1024 + c0;
    const unsigned* W0 = Wsrc + (long)(bn + r0)      * 1024 + c0;
    const unsigned* W1 = Wsrc + (long)(bn + r0 + 64) * 1024 + c0;

    const unsigned as_base = (unsigned)__cvta_generic_to_shared(As);
    const unsigned bs_base = (unsigned)__cvta_generic_to_shared(Bs);
    const unsigned soff0 = (unsigned)(( r0       * KPAD + c0) * 4);
    const unsigned soff1 = (unsigned)(((r0 + 64) * KPAD + c0) * 4);
    const unsigned stg_bytes = STG_ELEMS * 4;

    float acc[4][4][4];
    #pragma unroll
    for (int i = 0; i < 4; i++)
        #pragma unroll
        for (int j = 0; j < 4; j++)
            #pragma unroll
            for (int k = 0; k < 4; k++) acc[i][j][k] = 0.f;

    const int KT = 1024 / GBK;   // 64

    // prologue: issue tiles 0..2 into stages 0..2
    #pragma unroll
    for (int s = 0; s < 3; s++) {
        const unsigned so = (unsigned)s * stg_bytes;
        const int ko = s * GBK;
        cp_async16(as_base + so + soff0, A0 + ko);
        cp_async16(as_base + so + soff1, A1 + ko);
        cp_async16(bs_base + so + soff0, W0 + ko);
        cp_async16(bs_base + so + soff1, W1 + ko);
        cp_commit();
    }

    for (int t = 0; t < KT; ++t) {
        cp_wait2();          // oldest pending group (tile t) complete
        __syncthreads();     // visible to all; also closes stage reuse window

        const int stg = t & 3;
        const unsigned* as = As + stg * STG_ELEMS;
        const unsigned* bs = Bs + stg * STG_ELEMS;
        #pragma unroll
        for (int ks = 0; ks < 2; ks++) {
            const int kb = ks * 8;
            unsigned af[4][4], bf[4][2];
            #pragma unroll
            for (int mf = 0; mf < 4; mf++) {
                const int row = wm + mf * 16 + gp;
                af[mf][0] = as[ row      * KPAD + kb + tg];
                af[mf][1] = as[(row + 8) * KPAD + kb + tg];
                af[mf][2] = as[ row      * KPAD + kb + tg + 4];
                af[mf][3] = as[(row + 8) * KPAD + kb + tg + 4];
            }
            #pragma unroll
            for (int nf = 0; nf < 4; nf++) {
                const int row = wn + nf * 8 + gp;
                bf[nf][0] = bs[row * KPAD + kb + tg];
                bf[nf][1] = bs[row * KPAD + kb + tg + 4];
            }
            #pragma unroll
            for (int mf = 0; mf < 4; mf++)
                #pragma unroll
                for (int nf = 0; nf < 4; nf++)
                    mma8(acc[mf][nf], af[mf], bf[nf]);
        }

        if (t + 3 < KT) {
            const unsigned so = (unsigned)((t + 3) & 3) * stg_bytes;
            const int ko = (t + 3) * GBK;
            cp_async16(as_base + so + soff0, A0 + ko);
            cp_async16(as_base + so + soff1, A1 + ko);
            cp_async16(bs_base + so + soff0, W0 + ko);
            cp_async16(bs_base + so + soff1, W1 + ko);
            cp_commit();
        }
    }

    float* Cq = (dst == 0) ? g_q : (dst == 1) ? g_k : g_v;

    #pragma unroll
    for (int mf = 0; mf < 4; mf++) {
        #pragma unroll
        for (int nf = 0; nf < 4; nf++) {
            const int n0 = bn + wn + nf * 8 + tg * 2;
            const float b0 = bias[n0], b1 = bias[n0 + 1];
            #pragma unroll
            for (int half = 0; half < 2; half++) {
                const int m = bm + wm + mf * 16 + gp + half * 8;
                const float v0 = (acc[mf][nf][half * 2 + 0] + b0) * scale;
                const float v1 = (acc[mf][nf][half * 2 + 1] + b1) * scale;
                if (dst < 3) {
                    const int b = m >> 9, s = m & 511;
                    const int h = n0 >> 6, d = n0 & 63;
                    const long base = (((long)(b * NHEAD + h)) * SEQ + s) * HD;
                    Cq[base + d]     = v0;
                    Cq[base + d + 1] = v1;
                } else {
                    Cout[(long)m * HID + n0]     = v0;
                    Cout[(long)m * HID + n0 + 1] = v1;
                }
            }
        }
    }
}

// ===========================================================================
// tf32 mma fused attention (R10 best) — epilogue now writes tf32 bits to g_at
// (replaces the separate conv_attn pass; numerics identical).
// ===========================================================================
#define QT   32
#define SCP  516
#define KP   68
#define VP   72
#define KVBUF (64 * 72)
#define SMEM_ATTN ((QT*SCP + 2*KVBUF) * (int)sizeof(float))

__global__ __launch_bounds__(256, 2)
void attn_mma(const float* __restrict__ mask, const float* __restrict__ kg,
              const int* __restrict__ lena, const float* __restrict__ hy,
              const int* __restrict__ layer_p)
{
    extern __shared__ float sm[];
    float*    sc = sm;                              // [32][516]
    unsigned* kv = (unsigned*)(sm + QT * SCP);      // 2 buffers of 64x72

    const unsigned kv_u32 = (unsigned)__cvta_generic_to_shared(kv);

    const int tid = threadIdx.x;
    const int bh = blockIdx.x;
    const int b = bh >> 4, h = bh & 15;
    const int q0 = blockIdx.y * QT;

    const long head_off = ((long)(b * NHEAD + h)) * SEQ * HD;

    const int wid = tid >> 5, lane = tid & 31;
    const int g8 = lane >> 2;
    const int tg = lane & 3;
    const int wm = (wid >> 2) * 16;
    const int wn = (wid & 3) * 16;

    const int lr = tid >> 2;
    const int lcb = (tid & 3) * 16;

    unsigned qa[8][4];
    {
        const float* q_r0 = g_q + head_off + (long)(q0 + wm + g8)     * HD;
        const float* q_r1 = g_q + head_off + (long)(q0 + wm + g8 + 8) * HD;
        #pragma unroll
        for (int kb = 0; kb < 8; kb++) {
            qa[kb][0] = f2tf(q_r0[kb * 8 + tg]);
            qa[kb][1] = f2tf(q_r1[kb * 8 + tg]);
            qa[kb][2] = f2tf(q_r0[kb * 8 + tg + 4]);
            qa[kb][3] = f2tf(q_r1[kb * 8 + tg + 4]);
        }
    }

    // ================= Phase 1: scores = Q K^T + mask =================
    {
        const float* kbase = g_k + head_off + (long)lr * HD + lcb;
        const unsigned kdst = kv_u32 + (unsigned)((lr * KP + lcb) * 4);

        #pragma unroll
        for (int i = 0; i < 4; i++)
            cp_async16(kdst + i * 16, kbase + i * 4);
        cp_commit();
        cp_wait0();
        __syncthreads();

        for (int kt = 0; kt < 8; kt++) {
            if (kt < 7) {
                const unsigned d = kv_u32 + (unsigned)(((kt + 1) & 1) * KVBUF * 4)
                                 + (unsigned)((lr * KP + lcb) * 4);
                const float* s = kbase + (long)(kt + 1) * 64 * HD;
                #pragma unroll
                for (int i = 0; i < 4; i++)
                    cp_async16(d + i * 16, s + i * 4);
                cp_commit();
            }
            const unsigned* kbuf = kv + (kt & 1) * KVBUF;

            float acc[2][4];
            #pragma unroll
            for (int nf = 0; nf < 2; nf++)
                #pragma unroll
                for (int k = 0; k < 4; k++) acc[nf][k] = 0.f;

            #pragma unroll
            for (int kb = 0; kb < 8; kb++) {
                unsigned bf[2][2];
                #pragma unroll
                for (int nf = 0; nf < 2; nf++) {
                    const unsigned* base = kbuf + (wn + nf * 8 + g8) * KP + kb * 8 + tg;
                    bf[nf][0] = base[0];
                    bf[nf][1] = base[4];
                }
                #pragma unroll
                for (int nf = 0; nf < 2; nf++)
                    mma8(acc[nf], qa[kb], bf[nf]);
            }

            #pragma unroll
            for (int nf = 0; nf < 2; nf++) {
                const int c = kt * 64 + wn + nf * 8 + 2 * tg;
                #pragma unroll
                for (int half = 0; half < 2; half++) {
                    const int r = wm + g8 + half * 8;
                    const float2 mv = *(const float2*)(mask + ((long)b * SEQ + (q0 + r)) * SEQ + c);
                    float2 sv;
                    sv.x = acc[nf][half * 2 + 0] + mv.x;
                    sv.y = acc[nf][half * 2 + 1] + mv.y;
                    *(float2*)(sc + r * SCP + c) = sv;
                }
            }

            if (kt < 7) {
                cp_wait0();
                __syncthreads();
            }
        }
    }
    __syncthreads();

    // ================= Phase 2: softmax + probs mods =================
    {
        const int l  = lena[b];
        const int ly = *layer_p;
        const float ha = hy[ly * 3 + 0];
        const float hb = hy[ly * 3 + 1];
        const float hc = hy[ly * 3 + 2];
        const float* simp = kg + (long)b * 2 * SEQ * SEQ;
        const float* topp = simp + (long)SEQ * SEQ;

        for (int r = wid; r < QT; r += 8) {
            float* row = sc + r * SCP;
            const int qg = q0 + r;

            float mx = -1e30f;
            #pragma unroll
            for (int j0 = lane * 2; j0 < SEQ; j0 += 64) {
                const float2 v = *(const float2*)(row + j0);
                mx = fmaxf(mx, fmaxf(v.x, v.y));
            }
            #pragma unroll
            for (int o = 16; o > 0; o >>= 1) mx = fmaxf(mx, __shfl_xor_sync(0xffffffffu, mx, o));

            float s = 0.f;
            #pragma unroll
            for (int j0 = lane * 2; j0 < SEQ; j0 += 64) {
                float2 v = *(const float2*)(row + j0);
                v.x = __expf(v.x - mx);
                v.y = __expf(v.y - mx);
                *(float2*)(row + j0) = v;
                s += v.x + v.y;
            }
            #pragma unroll
            for (int o = 16; o > 0; o >>= 1) s += __shfl_xor_sync(0xffffffffu, s, o);
            const float inv = 1.0f / s;

            const bool ra_q = (qg >= 1) && (qg < l - 1);
            const bool ca_q = (qg >= l) && (qg < SEQ - 1);
            const long krow = (long)qg * SEQ;
            #pragma unroll
            for (int j0 = lane * 2; j0 < SEQ; j0 += 64) {
                float2 v = *(const float2*)(row + j0);
                const float2 sv = *(const float2*)(simp + krow + j0);
                const float2 tv = *(const float2*)(topp + krow + j0);
                const int j1 = j0 + 1;
                const bool ra_0 = (j0 >= 1) && (j0 < l - 1);
                const bool ca_0 = (j0 >= l) && (j0 < SEQ - 1);
                const bool ra_1 = (j1 >= 1) && (j1 < l - 1);
                const bool ca_1 = (j1 >= l) && (j1 < SEQ - 1);
                const float lg0 = ((ra_q && ca_0) || (ra_0 && ca_q)) ? hc : 1.0f;
                const float lg1 = ((ra_q && ca_1) || (ra_1 && ca_q)) ? hc : 1.0f;
                float2 p;
                p.x = __uint_as_float(f2tf(v.x * inv * lg0 + ha * sv.x + hb * tv.x));
                p.y = __uint_as_float(f2tf(v.y * inv * lg1 + ha * sv.y + hb * tv.y));
                *(float2*)(row + j0) = p;
            }
        }
    }

    // ================= Phase 3: out = P V =================
    {
        float oacc[2][4];
        #pragma unroll
        for (int nf = 0; nf < 2; nf++)
            #pragma unroll
            for (int k = 0; k < 4; k++) oacc[nf][k] = 0.f;

        const float* vbase = g_v + head_off + (long)lr * HD + lcb;
        const unsigned vdst = kv_u32 + (unsigned)((lr * VP + lcb) * 4);

        #pragma unroll
        for (int i = 0; i < 4; i++)
            cp_async16(vdst + i * 16, vbase + i * 4);
        cp_commit();
        cp_wait0();
        __syncthreads();

        for (int kt = 0; kt < 8; kt++) {
            if (kt < 7) {
                const unsigned d = kv_u32 + (unsigned)(((kt + 1) & 1) * KVBUF * 4)
                                 + (unsigned)((lr * VP + lcb) * 4);
                const float* s = vbase + (long)(kt + 1) * 64 * HD;
                #pragma unroll
                for (int i = 0; i < 4; i++)
                    cp_async16(d + i * 16, s + i * 4);
                cp_commit();
            }
            const unsigned* vbuf = kv + (kt & 1) * KVBUF;

            #pragma unroll
            for (int kb = 0; kb < 8; kb++) {
                unsigned af[4], bf[2][2];
                {
                    const float* base = sc + (wm + g8) * SCP + kt * 64 + kb * 8 + tg;
                    af[0] = __float_as_uint(base[0]);
                    af[1] = __float_as_uint(base[8 * SCP]);
                    af[2] = __float_as_uint(base[4]);
                    af[3] = __float_as_uint(base[8 * SCP + 4]);
                }
                #pragma unroll
                for (int nf = 0; nf < 2; nf++) {
                    const unsigned* base = vbuf + (kb * 8 + tg) * VP + wn + nf * 8 + g8;
                    bf[nf][0] = base[0];
                    bf[nf][1] = base[4 * VP];
                }
                #pragma unroll
                for (int nf = 0; nf < 2; nf++)
                    mma8(oacc[nf], af, bf[nf]);
            }

            if (kt < 7) {
                cp_wait0();
                __syncthreads();
            }
        }

        // epilogue: write tf32 bits directly to g_at [B,S,H]
        #pragma unroll
        for (int nf = 0; nf < 2; nf++) {
            const int d0 = wn + nf * 8 + 2 * tg;
            #pragma unroll
            for (int half = 0; half < 2; half++) {
                const int r = q0 + wm + g8 + half * 8;
                uint2 ov;
                ov.x = f2tf(oacc[nf][half * 2 + 0]);
                ov.y = f2tf(oacc[nf][half * 2 + 1]);
                *(uint2*)(g_at + ((long)b * SEQ + r) * HID + h * HD + d0) = ov;
            }
        }
    }
}

// ===========================================================================
extern "C" void kernel_launch(void* const* d_in, const int* in_sizes, int n_in,
                              void* d_out, int out_size)
{
    const float* query = (const float*)d_in[0];
    const float* key   = (const float*)d_in[1];
    const float* value = (const float*)d_in[2];
    const float* mask  = (const float*)d_in[3];
    const int*   lena  = (const int*)  d_in[4];
    const float* kg    = (const float*)d_in[5];
    const float* hy    = (const float*)d_in[6];
    const int*   layer = (const int*)  d_in[7];
    const float* Wq    = (const float*)d_in[8];
    const float* bq    = (const float*)d_in[9];
    const float* Wk    = (const float*)d_in[10];
    const float* bk    = (const float*)d_in[11];
    const float* Wv    = (const float*)d_in[12];
    const float* bv    = (const float*)d_in[13];
    const float* Wo    = (const float*)d_in[14];
    const float* bo    = (const float*)d_in[15];
    float* out = (float*)d_out;

    static int smem_set = 0;
    if (!smem_set) {
        cudaFuncSetAttribute(attn_mma,
                             cudaFuncAttributeMaxDynamicSharedMemorySize, SMEM_ATTN);
        cudaFuncSetAttribute(gemm_tf32,
                             cudaFuncAttributeMaxDynamicSharedMemorySize, SMEM_GEMM);
        smem_set = 1;
    }

    const dim3 ggrid(HID / 128, MROWS / 128);   // (8, 32)
    const float qscale = 0.125f;                // 1/sqrt(64)

    conv_inputs<<<4096, 256>>>(query, key, value, Wq, Wk, Wv, Wo);

    gemm_tf32<<<ggrid, 256, SMEM_GEMM>>>(0, 0, bq, nullptr, qscale, 0);
    gemm_tf32<<<ggrid, 256, SMEM_GEMM>>>(1, 1, bk, nullptr, 1.0f,   1);
    gemm_tf32<<<ggrid, 256, SMEM_GEMM>>>(2, 2, bv, nullptr, 1.0f,   2);

    dim3 attn_grid(BATCH * NHEAD, SEQ / QT);    // (128, 16)
    attn_mma<<<attn_grid, 256, SMEM_ATTN>>>(mask, kg, lena, hy, layer);

    gemm_tf32<<<ggrid, 256, SMEM_GEMM>>>(3, 3, bo, out, 1.0f, 3);
}